// round 4
// baseline (speedup 1.0000x reference)
#include <cuda_runtime.h>
#include <cuda_bf16.h>
#include <cstdint>

// Inputs (metadata order):
//   d_in[0]: output  float32  [16, 512, 32000]  (B*S = 8192 rows, V = 32000)
//   d_in[1]: target  int32    [16, 512]
// Output: scalar float32 = sum(target!=0 ? -log(p_target) : 0) / count(target!=0)

#define ROWS     8192
#define VOCAB    32000
#define NBLOCKS  64
#define NTHREADS 128          // 1 row per thread

// Fixed-point accumulator: partial_sum * 2^32 as u64. Max total < 2^49.
__device__ unsigned long long g_acc_sum;   // zero-init; finalizer resets
__device__ unsigned int       g_acc_cnt;   // zero-init; finalizer resets
__device__ unsigned int       g_ticket;    // zero-init; finalizer resets

__global__ __launch_bounds__(NTHREADS, 1)
void nll_gather_kernel(const float* __restrict__ out_probs,
                       const int* __restrict__ target,
                       float* __restrict__ result)
{
    const int tid = threadIdx.x;
    const int row = blockIdx.x * NTHREADS + tid;

    // Dependent chain: target load -> gather (inherent 2x DRAM latency)
    const int t = target[row];
    const float p = __ldg(&out_probs[(size_t)row * VOCAB + t]);

    float lsum = (t != 0) ? -__logf(p) : 0.0f;
    int   lcnt = (t != 0) ? 1 : 0;

    // Warp shuffle reduction
    #pragma unroll
    for (int off = 16; off > 0; off >>= 1) {
        lsum += __shfl_down_sync(0xFFFFFFFFu, lsum, off);
        lcnt += __shfl_down_sync(0xFFFFFFFFu, lcnt, off);
    }

    __shared__ float s_sum[NTHREADS / 32];
    __shared__ int   s_cnt[NTHREADS / 32];
    __shared__ bool  s_last;
    const int warp = tid >> 5;
    const int lane = tid & 31;
    if (lane == 0) { s_sum[warp] = lsum; s_cnt[warp] = lcnt; }
    __syncthreads();

    if (tid == 0) {
        float vs = s_sum[0] + s_sum[1] + s_sum[2] + s_sum[3];
        int   vc = s_cnt[0] + s_cnt[1] + s_cnt[2] + s_cnt[3];

        // Deterministic integer accumulation: fixed point, scale 2^32.
        unsigned long long fx =
            (unsigned long long)((double)vs * 4294967296.0);
        atomicAdd(&g_acc_sum, fx);
        atomicAdd(&g_acc_cnt, (unsigned int)vc);
        __threadfence();
        unsigned old = atomicAdd(&g_ticket, 1u);
        s_last = (old == NBLOCKS - 1);
    }
    __syncthreads();

    // Last-arriving block finalizes: 2 reads + divide + reset.
    if (s_last && tid == 0) {
        unsigned long long s = atomicAdd(&g_acc_sum, 0ULL);
        unsigned int       c = atomicAdd(&g_acc_cnt, 0u);
        double sum = (double)s * (1.0 / 4294967296.0);
        result[0] = (float)(sum / (double)c);
        // Reset for next graph replay (replay launches are ordered).
        g_acc_sum = 0ULL;
        g_acc_cnt = 0u;
        g_ticket  = 0u;
        __threadfence();
    }
}

extern "C" void kernel_launch(void* const* d_in, const int* in_sizes, int n_in,
                              void* d_out, int out_size)
{
    const float* probs  = (const float*)d_in[0];
    const int*   target = (const int*)d_in[1];
    float*       result = (float*)d_out;

    nll_gather_kernel<<<NBLOCKS, NTHREADS>>>(probs, target, result);
}

// round 5
// speedup vs baseline: 1.3014x; 1.3014x over previous
#include <cuda_runtime.h>
#include <cuda_bf16.h>
#include <cstdint>

// Inputs (metadata order):
//   d_in[0]: output  float32  [16, 512, 32000]  (B*S = 8192 rows, V = 32000)
//   d_in[1]: target  int32    [16, 512]
// Output: scalar float32 = sum(target!=0 ? -log(p_target) : 0) / count(target!=0)

#define ROWS     8192
#define VOCAB    32000
#define NBLOCKS  32
#define NTHREADS 256          // 1 row per thread

__device__ float    g_sum[NBLOCKS];
__device__ float    g_cnt[NBLOCKS];
__device__ unsigned g_ticket;   // zero-initialized; finalizer resets to 0

__global__ __launch_bounds__(NTHREADS, 1)
void nll_gather_kernel(const float* __restrict__ out_probs,
                       const int* __restrict__ target,
                       float* __restrict__ result)
{
    const int tid = threadIdx.x;
    const int bid = blockIdx.x;
    const int row = bid * NTHREADS + tid;

    // Dependent chain: target load -> gather (2x DRAM latency, unavoidable)
    const int t = target[row];
    const float p = __ldg(&out_probs[(size_t)row * VOCAB + t]);

    float lsum = (t != 0) ? -__logf(p) : 0.0f;
    float lcnt = (t != 0) ? 1.0f : 0.0f;

    // Warp shuffle reduction
    #pragma unroll
    for (int off = 16; off > 0; off >>= 1) {
        lsum += __shfl_down_sync(0xFFFFFFFFu, lsum, off);
        lcnt += __shfl_down_sync(0xFFFFFFFFu, lcnt, off);
    }

    __shared__ float s_sum[NTHREADS / 32];
    __shared__ float s_cnt[NTHREADS / 32];
    __shared__ bool  s_last;
    const int warp = tid >> 5;
    const int lane = tid & 31;
    if (lane == 0) { s_sum[warp] = lsum; s_cnt[warp] = lcnt; }
    __syncthreads();

    if (tid == 0) {
        float vs = 0.0f, vc = 0.0f;
        #pragma unroll
        for (int w = 0; w < NTHREADS / 32; ++w) { vs += s_sum[w]; vc += s_cnt[w]; }
        g_sum[bid] = vs;          // independent addresses: no serialization
        g_cnt[bid] = vc;
        __threadfence();          // publish partials before ticket
        unsigned old = atomicAdd(&g_ticket, 1u);
        s_last = (old == NBLOCKS - 1);
    }
    __syncthreads();

    // Last-arriving block finalizes with warp-parallel loads + shuffle tree.
    // Fixed lane->index mapping + fixed shuffle order => deterministic.
    if (s_last && warp < 2) {
        float v = (warp == 0) ? g_sum[lane] : g_cnt[lane];  // 32 parallel loads
        #pragma unroll
        for (int off = 16; off > 0; off >>= 1)
            v += __shfl_down_sync(0xFFFFFFFFu, v, off);

        __shared__ float s_fin[2];
        if (lane == 0) s_fin[warp] = v;
        __syncwarp();
        // warp 0 lane 0 waits for warp 1 via a tiny spin on shared flag is
        // racy; instead use named barrier across the two warps:
        asm volatile("bar.sync 1, 64;" ::: "memory");
        if (warp == 0 && lane == 0) {
            result[0] = s_fin[0] / s_fin[1];
            g_ticket = 0;        // reset for next graph replay
            __threadfence();
        }
    }
}

extern "C" void kernel_launch(void* const* d_in, const int* in_sizes, int n_in,
                              void* d_out, int out_size)
{
    const float* probs  = (const float*)d_in[0];
    const int*   target = (const int*)d_in[1];
    float*       result = (float*)d_out;

    nll_gather_kernel<<<NBLOCKS, NTHREADS>>>(probs, target, result);
}

// round 6
// speedup vs baseline: 1.3140x; 1.0097x over previous
#include <cuda_runtime.h>
#include <cuda_bf16.h>
#include <cstdint>

// Inputs (metadata order):
//   d_in[0]: output  float32  [16, 512, 32000]  (B*S = 8192 rows, V = 32000)
//   d_in[1]: target  int32    [16, 512]
// Output: scalar float32 = sum(target!=0 ? -log(p_target) : 0) / count(target!=0)

#define ROWS     8192
#define VOCAB    32000
#define NBLOCKS  32
#define NTHREADS 256          // 1 row per thread
#define NWARPS   (NTHREADS / 32)

__device__ float2   g_part[NBLOCKS];   // (sum, cnt) per block
__device__ unsigned g_ticket;          // zero-init; finalizer resets

__global__ __launch_bounds__(NTHREADS, 1)
void nll_gather_kernel(const float* __restrict__ out_probs,
                       const int* __restrict__ target,
                       float* __restrict__ result)
{
    const int tid = threadIdx.x;
    const int bid = blockIdx.x;
    const int row = bid * NTHREADS + tid;

    // Dependent chain: target load -> gather (2x memory latency, inherent)
    const int t = target[row];
    const float p = __ldcg(&out_probs[(size_t)row * VOCAB + t]);

    float lsum = (t != 0) ? -__logf(p) : 0.0f;
    float lcnt = (t != 0) ? 1.0f : 0.0f;

    // Warp shuffle reduction
    #pragma unroll
    for (int off = 16; off > 0; off >>= 1) {
        lsum += __shfl_down_sync(0xFFFFFFFFu, lsum, off);
        lcnt += __shfl_down_sync(0xFFFFFFFFu, lcnt, off);
    }

    __shared__ float2 s_part[NWARPS];
    const int warp = tid >> 5;
    const int lane = tid & 31;
    if (lane == 0) s_part[warp] = make_float2(lsum, lcnt);
    __syncthreads();   // the only block-wide barrier

    // Entire epilogue lives in warp 0.
    if (warp == 0) {
        float2 v = (lane < NWARPS) ? s_part[lane] : make_float2(0.f, 0.f);
        #pragma unroll
        for (int off = NWARPS / 2; off > 0; off >>= 1) {
            v.x += __shfl_down_sync(0xFFFFFFFFu, v.x, off);
            v.y += __shfl_down_sync(0xFFFFFFFFu, v.y, off);
        }

        unsigned old = 0u;
        if (lane == 0) {
            g_part[bid] = v;   // independent address: STG.64, no contention
            // Release orders the partial store; acquire orders finalize loads.
            // No gpu-scope membar / L1D flush needed.
            asm volatile("atom.acq_rel.gpu.global.add.u32 %0, [%1], %2;"
                         : "=r"(old)
                         : "l"(&g_ticket), "r"(1u)
                         : "memory");
        }
        old = __shfl_sync(0xFFFFFFFFu, old, 0);

        // Last-arriving block finalizes: 32 parallel L2 loads + shuffle tree.
        if (old == NBLOCKS - 1) {
            float2 f = __ldcg(&g_part[lane]);     // lane i -> block i partial
            #pragma unroll
            for (int off = 16; off > 0; off >>= 1) {
                f.x += __shfl_down_sync(0xFFFFFFFFu, f.x, off);
                f.y += __shfl_down_sync(0xFFFFFFFFu, f.y, off);
            }
            if (lane == 0) {
                result[0] = f.x / f.y;
                g_ticket = 0;   // reset for next graph replay
            }
        }
    }
}

extern "C" void kernel_launch(void* const* d_in, const int* in_sizes, int n_in,
                              void* d_out, int out_size)
{
    const float* probs  = (const float*)d_in[0];
    const int*   target = (const int*)d_in[1];
    float*       result = (float*)d_out;

    nll_gather_kernel<<<NBLOCKS, NTHREADS>>>(probs, target, result);
}